// round 2
// baseline (speedup 1.0000x reference)
#include <cuda_runtime.h>
#include <cstdint>

// ---------------------------------------------------------------------------
// out = relu(x @ W_ih^T + (h0@W_hh^T + b_ih + b_hh)) @ W_out + b_out
// tf32 mma.sync.m16n8k8 pipeline (baseline PTX; tcgen05 unavailable: harness
// compiles PTX at target sm_103, not sm_103a).
//
// Per 128-row tile:
//   GEMM1: h[128,128] = x[128,64] @ W_ih^T     (A = x frags, B = W_ih packed)
//   relu + hidden-drive + cvt, C-frag -> A-frag via register shuffles
//   GEMM2: out[128,32] = h @ W_out             (B = W_out packed)
// W fragment packs built once per CTA in smem; h never touches smem.
// ---------------------------------------------------------------------------

static constexpr int NIN      = 64;
static constexpr int NH       = 128;
static constexpr int NOUT     = 32;
static constexpr int TILE_M   = 128;
static constexpr int T_TOTAL  = 1048576;
static constexpr int NTILES   = T_TOTAL / TILE_M;   // 8192
static constexpr int GRID     = 304;                // 2 CTAs/SM x 152 SMs
static constexpr int KTHREADS = 128;                // 4 warps

// x smem tile: 128 rows x 64 cols, pair-packed (k, k+4) float2s, row pitch 72
// floats (288 B) for conflict-free LDS.64 A-fragment reads.
static constexpr int XPITCH = 72;

// ---- smem byte offsets ----
static constexpr int SM_C   = 0;                    // 128 f32 hidden drive
static constexpr int SM_BO  = 512;                  // 32 f32 b_out
static constexpr int SM_B1  = 1024;                 // W_ih B-frag pack, 32 KB
static constexpr int SM_B2  = SM_B1 + 32768;        // W_out B-frag pack, 16 KB
static constexpr int SM_X   = SM_B2 + 16384;        // x tile, 128*72*4 = 36864
static constexpr int SMEM_BYTES = SM_X + TILE_M * XPITCH * 4;   // 87040

__device__ __forceinline__ uint32_t f2tf(float f) {   // fp32 -> tf32 (RNA)
    uint32_t u;
    asm("cvt.rna.tf32.f32 %0, %1;" : "=r"(u) : "f"(f));
    return u;
}

__device__ __forceinline__ void mma_tf32(float& d0, float& d1, float& d2, float& d3,
                                         uint32_t a0, uint32_t a1, uint32_t a2, uint32_t a3,
                                         uint32_t b0, uint32_t b1) {
    asm volatile(
        "mma.sync.aligned.m16n8k8.row.col.f32.tf32.tf32.f32 "
        "{%0,%1,%2,%3}, {%4,%5,%6,%7}, {%8,%9}, {%0,%1,%2,%3};"
        : "+f"(d0), "+f"(d1), "+f"(d2), "+f"(d3)
        : "r"(a0), "r"(a1), "r"(a2), "r"(a3), "r"(b0), "r"(b1));
}

// ---------------------------------------------------------------------------
__global__ void __launch_bounds__(KTHREADS)
rnn_model_kernel(const float* __restrict__ x,
                 const float* __restrict__ W_ih,
                 const float* __restrict__ W_hh,
                 const float* __restrict__ b_ih,
                 const float* __restrict__ b_hh,
                 const float* __restrict__ W_out,
                 const float* __restrict__ b_out,
                 const float* __restrict__ h0,
                 float* __restrict__ out)
{
    extern __shared__ char smem[];
    const int tid  = threadIdx.x;
    const int wid  = tid >> 5;
    const int lane = tid & 31;
    const int g    = lane >> 2;   // group (row within fragment)
    const int o    = lane & 3;    // thread-in-group (col within fragment)

    uint2*  B1 = reinterpret_cast<uint2*>(smem + SM_B1);   // [8k][16n][32] (b0,b1)
    uint2*  B2 = reinterpret_cast<uint2*>(smem + SM_B2);   // [16k][4n][32]
    float*  Cd = reinterpret_cast<float*>(smem + SM_C);
    float2* C2 = reinterpret_cast<float2*>(smem + SM_C);
    float2* BO = reinterpret_cast<float2*>(smem + SM_BO);
    uint32_t* XS = reinterpret_cast<uint32_t*>(smem + SM_X);

    // ---- one-time per-CTA packs ----
    // W_ih B-fragments: b0 = W_ih[n0+l/4][k0+l%4], b1 = +4 cols
    for (int e = tid; e < 8 * 16 * 32; e += KTHREADS) {
        int kj = e >> 9, nj = (e >> 5) & 15, l = e & 31;
        int row = nj * 8 + (l >> 2), col = kj * 8 + (l & 3);
        const float* p = W_ih + row * NIN + col;
        B1[e] = make_uint2(f2tf(p[0]), f2tf(p[4]));
    }
    // W_out B-fragments: b0 = W_out[k0+l%4][n0+l/4], b1 = +4 rows
    for (int e = tid; e < 16 * 4 * 32; e += KTHREADS) {
        int kj = e >> 7, t = (e >> 5) & 3, l = e & 31;
        int row = kj * 8 + (l & 3), col = t * 8 + (l >> 2);
        const float* p = W_out + row * NOUT + col;
        B2[e] = make_uint2(f2tf(p[0]), f2tf(p[NOUT * 4]));
    }
    // hidden drive c = h0 @ W_hh^T + b_ih + b_hh (fp32 exact)
    {
        float c = b_ih[tid] + b_hh[tid];
        const float4* hh = reinterpret_cast<const float4*>(W_hh + (size_t)tid * NH);
        const float4* h4 = reinterpret_cast<const float4*>(h0);
        #pragma unroll 8
        for (int q = 0; q < NH / 4; q++) {
            float4 w = hh[q], h = h4[q];
            c += w.x * h.x + w.y * h.y + w.z * h.z + w.w * h.w;
        }
        Cd[tid] = c;
        if (tid < NOUT / 2) BO[tid] = make_float2(b_out[2 * tid], b_out[2 * tid + 1]);
    }
    __syncthreads();

    const uint32_t src1 = (uint32_t)((lane & ~3) | (o >> 1));
    const uint32_t src2 = src1 + 2;
    const bool     odd  = (o & 1) != 0;

    for (int tile = blockIdx.x; tile < NTILES; tile += GRID) {
        // ---- stage x tile: gmem -> tf32 pair-packed smem ----
        const float4* xp = reinterpret_cast<const float4*>(
            x + (size_t)tile * (TILE_M * NIN));
        #pragma unroll
        for (int i = 0; i < 8; i++) {
            int j = i * KTHREADS + tid;            // j = row*8 + ktile
            float4 v0 = xp[2 * j];
            float4 v1 = xp[2 * j + 1];
            int off = (j >> 3) * XPITCH + (j & 7) * 8;
            uint4 p0 = { f2tf(v0.x), f2tf(v1.x), f2tf(v0.y), f2tf(v1.y) };
            uint4 p1 = { f2tf(v0.z), f2tf(v1.z), f2tf(v0.w), f2tf(v1.w) };
            *reinterpret_cast<uint4*>(XS + off)     = p0;
            *reinterpret_cast<uint4*>(XS + off + 4) = p1;
        }
        __syncthreads();

        #pragma unroll
        for (int mt = 0; mt < 2; mt++) {
            const int m0 = (wid * 2 + mt) * 16;

            // ---- A1 fragments for this 16-row slab (x) ----
            uint2 a_lo[8], a_hi[8];
            {
                const uint32_t* p0 = XS + (m0 + g) * XPITCH + 2 * o;
                const uint32_t* p1 = p0 + 8 * XPITCH;
                #pragma unroll
                for (int k = 0; k < 8; k++) {
                    a_lo[k] = *reinterpret_cast<const uint2*>(p0 + k * 8);
                    a_hi[k] = *reinterpret_cast<const uint2*>(p1 + k * 8);
                }
            }

            // ---- GEMM1 + relu + frag conversion -> A2 ----
            uint32_t A2[16][4];
            #pragma unroll
            for (int j = 0; j < 16; j++) {
                float d0 = 0.f, d1 = 0.f, d2 = 0.f, d3 = 0.f;
                #pragma unroll
                for (int k = 0; k < 8; k++) {
                    uint2 b = B1[(k * 16 + j) * 32 + lane];
                    mma_tf32(d0, d1, d2, d3,
                             a_lo[k].x, a_hi[k].x, a_lo[k].y, a_hi[k].y,
                             b.x, b.y);
                }
                float2 cd = C2[j * 4 + o];
                uint32_t r0 = f2tf(fmaxf(d0 + cd.x, 0.f));
                uint32_t r1 = f2tf(fmaxf(d1 + cd.y, 0.f));
                uint32_t r2 = f2tf(fmaxf(d2 + cd.x, 0.f));
                uint32_t r3 = f2tf(fmaxf(d3 + cd.y, 0.f));
                // C-frag (m16n8) -> A-frag (m16k8)
                uint32_t t0, t1;
                t0 = __shfl_sync(0xffffffffu, r0, src1);
                t1 = __shfl_sync(0xffffffffu, r1, src1);
                A2[j][0] = odd ? t1 : t0;
                t0 = __shfl_sync(0xffffffffu, r0, src2);
                t1 = __shfl_sync(0xffffffffu, r1, src2);
                A2[j][2] = odd ? t1 : t0;
                t0 = __shfl_sync(0xffffffffu, r2, src1);
                t1 = __shfl_sync(0xffffffffu, r3, src1);
                A2[j][1] = odd ? t1 : t0;
                t0 = __shfl_sync(0xffffffffu, r2, src2);
                t1 = __shfl_sync(0xffffffffu, r3, src2);
                A2[j][3] = odd ? t1 : t0;
            }

            // ---- GEMM2: out slab = h @ W_out ----
            const size_t row0 = (size_t)tile * TILE_M + m0 + g;
            #pragma unroll
            for (int t = 0; t < 4; t++) {
                float e0 = 0.f, e1 = 0.f, e2 = 0.f, e3 = 0.f;
                #pragma unroll
                for (int j = 0; j < 16; j++) {
                    uint2 b = B2[(j * 4 + t) * 32 + lane];
                    mma_tf32(e0, e1, e2, e3,
                             A2[j][0], A2[j][1], A2[j][2], A2[j][3],
                             b.x, b.y);
                }
                float2 bo = BO[t * 4 + o];
                float2 v0 = { e0 + bo.x, e1 + bo.y };
                float2 v1 = { e2 + bo.x, e3 + bo.y };
                int col = t * 8 + 2 * o;
                *reinterpret_cast<float2*>(out + row0 * NOUT + col)       = v0;
                *reinterpret_cast<float2*>(out + (row0 + 8) * NOUT + col) = v1;
            }
        }
        __syncthreads();   // protect XS before next tile's staging
    }
}

// ---------------------------------------------------------------------------
extern "C" void kernel_launch(void* const* d_in, const int* in_sizes, int n_in,
                              void* d_out, int out_size) {
    const float* x     = (const float*)d_in[0];
    const float* W_ih  = (const float*)d_in[1];
    const float* W_hh  = (const float*)d_in[2];
    const float* b_ih  = (const float*)d_in[3];
    const float* b_hh  = (const float*)d_in[4];
    const float* W_out = (const float*)d_in[5];
    const float* b_out = (const float*)d_in[6];
    const float* h0    = (const float*)d_in[7];
    float* out = (float*)d_out;

    cudaFuncSetAttribute(rnn_model_kernel,
                         cudaFuncAttributeMaxDynamicSharedMemorySize, SMEM_BYTES);
    rnn_model_kernel<<<GRID, KTHREADS, SMEM_BYTES>>>(
        x, W_ih, W_hh, b_ih, b_hh, W_out, b_out, h0, out);
}

// round 3
// speedup vs baseline: 1.0058x; 1.0058x over previous
#include <cuda_runtime.h>
#include <cstdint>

// ---------------------------------------------------------------------------
// out = relu(x @ W_ih^T + (h0@W_hh^T + b_ih + b_hh)) @ W_out + b_out
// tf32 mma.sync.m16n8k8, fused two-GEMM pipeline.
// 256 threads/CTA (8 warps, one 16-row slab each), 128-row tiles.
// GEMM2 fused into GEMM1 j-loop: h fragment never stored (no A2 array).
// ---------------------------------------------------------------------------

static constexpr int NIN      = 64;
static constexpr int NH       = 128;
static constexpr int NOUT     = 32;
static constexpr int TILE_M   = 128;
static constexpr int T_TOTAL  = 1048576;
static constexpr int NTILES   = T_TOTAL / TILE_M;   // 8192
static constexpr int GRID     = 304;                // 2 CTAs/SM x 152 SMs
static constexpr int KTHREADS = 256;                // 8 warps

// x smem tile: 128 rows x 64 cols, pair-packed (k, k+4) float2s, row pitch 72
// floats (288 B) for conflict-free LDS.64 A-fragment reads.
static constexpr int XPITCH = 72;

// ---- smem byte offsets ----
static constexpr int SM_C   = 0;                    // 128 f32 hidden drive
static constexpr int SM_BO  = 512;                  // 32 f32 b_out
static constexpr int SM_B1  = 1024;                 // W_ih B-frag pack, 32 KB
static constexpr int SM_B2  = SM_B1 + 32768;        // W_out B-frag pack, 16 KB
static constexpr int SM_X   = SM_B2 + 16384;        // x tile, 128*72*4 = 36864
static constexpr int SMEM_BYTES = SM_X + TILE_M * XPITCH * 4;   // 87040

__device__ __forceinline__ uint32_t f2tf(float f) {   // fp32 -> tf32 (RNA)
    uint32_t u;
    asm("cvt.rna.tf32.f32 %0, %1;" : "=r"(u) : "f"(f));
    return u;
}

__device__ __forceinline__ void mma_tf32(float& d0, float& d1, float& d2, float& d3,
                                         uint32_t a0, uint32_t a1, uint32_t a2, uint32_t a3,
                                         uint32_t b0, uint32_t b1) {
    asm volatile(
        "mma.sync.aligned.m16n8k8.row.col.f32.tf32.tf32.f32 "
        "{%0,%1,%2,%3}, {%4,%5,%6,%7}, {%8,%9}, {%0,%1,%2,%3};"
        : "+f"(d0), "+f"(d1), "+f"(d2), "+f"(d3)
        : "r"(a0), "r"(a1), "r"(a2), "r"(a3), "r"(b0), "r"(b1));
}

// ---------------------------------------------------------------------------
__global__ void __launch_bounds__(KTHREADS, 2)
rnn_model_kernel(const float* __restrict__ x,
                 const float* __restrict__ W_ih,
                 const float* __restrict__ W_hh,
                 const float* __restrict__ b_ih,
                 const float* __restrict__ b_hh,
                 const float* __restrict__ W_out,
                 const float* __restrict__ b_out,
                 const float* __restrict__ h0,
                 float* __restrict__ out)
{
    extern __shared__ char smem[];
    const int tid  = threadIdx.x;
    const int wid  = tid >> 5;
    const int lane = tid & 31;
    const int g    = lane >> 2;   // group (row within fragment)
    const int o    = lane & 3;    // thread-in-group

    uint2*  B1 = reinterpret_cast<uint2*>(smem + SM_B1);   // [8k][16n][32]
    uint2*  B2 = reinterpret_cast<uint2*>(smem + SM_B2);   // [16k][4n][32]
    float*  Cd = reinterpret_cast<float*>(smem + SM_C);
    float2* C2 = reinterpret_cast<float2*>(smem + SM_C);
    float2* BO = reinterpret_cast<float2*>(smem + SM_BO);
    uint32_t* XS = reinterpret_cast<uint32_t*>(smem + SM_X);

    // ---- one-time per-CTA packs ----
    for (int e = tid; e < 8 * 16 * 32; e += KTHREADS) {
        int kj = e >> 9, nj = (e >> 5) & 15, l = e & 31;
        int row = nj * 8 + (l >> 2), col = kj * 8 + (l & 3);
        const float* p = W_ih + row * NIN + col;
        B1[e] = make_uint2(f2tf(p[0]), f2tf(p[4]));
    }
    for (int e = tid; e < 16 * 4 * 32; e += KTHREADS) {
        int kj = e >> 7, t = (e >> 5) & 3, l = e & 31;
        int row = kj * 8 + (l & 3), col = t * 8 + (l >> 2);
        const float* p = W_out + row * NOUT + col;
        B2[e] = make_uint2(f2tf(p[0]), f2tf(p[NOUT * 4]));
    }
    if (tid < NH) {
        float c = b_ih[tid] + b_hh[tid];
        const float4* hh = reinterpret_cast<const float4*>(W_hh + (size_t)tid * NH);
        const float4* h4 = reinterpret_cast<const float4*>(h0);
        #pragma unroll 8
        for (int q = 0; q < NH / 4; q++) {
            float4 w = hh[q], h = h4[q];
            c += w.x * h.x + w.y * h.y + w.z * h.z + w.w * h.w;
        }
        Cd[tid] = c;
    }
    if (tid < NOUT / 2) BO[tid] = make_float2(b_out[2 * tid], b_out[2 * tid + 1]);
    __syncthreads();

    const uint32_t src1 = (uint32_t)((lane & ~3) | (o >> 1));
    const uint32_t src2 = src1 + 2;
    const bool     odd  = (o & 1) != 0;
    const int      m0   = wid * 16;                 // one slab per warp

    for (int tile = blockIdx.x; tile < NTILES; tile += GRID) {
        // ---- stage x tile: gmem -> tf32 pair-packed smem (coalesced) ----
        const float4* xp = reinterpret_cast<const float4*>(
            x + (size_t)tile * (TILE_M * NIN));
        #pragma unroll
        for (int i = 0; i < 4; i++) {
            int j = i * KTHREADS + tid;            // j = row*8 + ktile
            float4 v0 = xp[2 * j];
            float4 v1 = xp[2 * j + 1];
            int off = (j >> 3) * XPITCH + (j & 7) * 8;
            uint4 p0 = { f2tf(v0.x), f2tf(v1.x), f2tf(v0.y), f2tf(v1.y) };
            uint4 p1 = { f2tf(v0.z), f2tf(v1.z), f2tf(v0.w), f2tf(v1.w) };
            *reinterpret_cast<uint4*>(XS + off)     = p0;
            *reinterpret_cast<uint4*>(XS + off + 4) = p1;
        }
        __syncthreads();

        // ---- A1 fragments for this warp's 16-row slab ----
        uint2 a_lo[8], a_hi[8];
        {
            const uint32_t* p0 = XS + (m0 + g) * XPITCH + 2 * o;
            const uint32_t* p1 = p0 + 8 * XPITCH;
            #pragma unroll
            for (int k = 0; k < 8; k++) {
                a_lo[k] = *reinterpret_cast<const uint2*>(p0 + k * 8);
                a_hi[k] = *reinterpret_cast<const uint2*>(p1 + k * 8);
            }
        }

        // ---- fused GEMM1 -> relu/convert -> GEMM2 accumulate ----
        float e0[4] = {0.f, 0.f, 0.f, 0.f};
        float e1[4] = {0.f, 0.f, 0.f, 0.f};
        float e2[4] = {0.f, 0.f, 0.f, 0.f};
        float e3[4] = {0.f, 0.f, 0.f, 0.f};

        #pragma unroll
        for (int j = 0; j < 16; j++) {
            // GEMM1 chunk: two independent 4-deep accumulation chains
            float da0 = 0.f, da1 = 0.f, da2 = 0.f, da3 = 0.f;
            float db0 = 0.f, db1 = 0.f, db2 = 0.f, db3 = 0.f;
            #pragma unroll
            for (int k = 0; k < 4; k++) {
                uint2 b = B1[(k * 16 + j) * 32 + lane];
                mma_tf32(da0, da1, da2, da3,
                         a_lo[k].x, a_hi[k].x, a_lo[k].y, a_hi[k].y, b.x, b.y);
            }
            #pragma unroll
            for (int k = 4; k < 8; k++) {
                uint2 b = B1[(k * 16 + j) * 32 + lane];
                mma_tf32(db0, db1, db2, db3,
                         a_lo[k].x, a_hi[k].x, a_lo[k].y, a_hi[k].y, b.x, b.y);
            }
            float2 cd = C2[j * 4 + o];
            uint32_t r0 = f2tf(fmaxf(da0 + db0 + cd.x, 0.f));
            uint32_t r1 = f2tf(fmaxf(da1 + db1 + cd.y, 0.f));
            uint32_t r2 = f2tf(fmaxf(da2 + db2 + cd.x, 0.f));
            uint32_t r3 = f2tf(fmaxf(da3 + db3 + cd.y, 0.f));

            // C-frag (m16n8) -> A-frag (m16k8) via shuffles (transient)
            uint32_t A0, A1, A2r, A3, t0, t1;
            t0 = __shfl_sync(0xffffffffu, r0, src1);
            t1 = __shfl_sync(0xffffffffu, r1, src1);
            A0 = odd ? t1 : t0;
            t0 = __shfl_sync(0xffffffffu, r0, src2);
            t1 = __shfl_sync(0xffffffffu, r1, src2);
            A2r = odd ? t1 : t0;
            t0 = __shfl_sync(0xffffffffu, r2, src1);
            t1 = __shfl_sync(0xffffffffu, r3, src1);
            A1 = odd ? t1 : t0;
            t0 = __shfl_sync(0xffffffffu, r2, src2);
            t1 = __shfl_sync(0xffffffffu, r3, src2);
            A3 = odd ? t1 : t0;

            // GEMM2 accumulate: 4 output n-tiles
            {
                uint2 b = B2[(j * 4 + 0) * 32 + lane];
                mma_tf32(e0[0], e0[1], e0[2], e0[3], A0, A1, A2r, A3, b.x, b.y);
            }
            {
                uint2 b = B2[(j * 4 + 1) * 32 + lane];
                mma_tf32(e1[0], e1[1], e1[2], e1[3], A0, A1, A2r, A3, b.x, b.y);
            }
            {
                uint2 b = B2[(j * 4 + 2) * 32 + lane];
                mma_tf32(e2[0], e2[1], e2[2], e2[3], A0, A1, A2r, A3, b.x, b.y);
            }
            {
                uint2 b = B2[(j * 4 + 3) * 32 + lane];
                mma_tf32(e3[0], e3[1], e3[2], e3[3], A0, A1, A2r, A3, b.x, b.y);
            }
        }

        // ---- epilogue: + b_out, coalesced float2 stores ----
        {
            const size_t row0 = (size_t)tile * TILE_M + m0 + g;
            float* orow0 = out + row0 * NOUT + 2 * o;
            float* orow1 = out + (row0 + 8) * NOUT + 2 * o;
            float2 bo;
            bo = BO[0 * 4 + o];
            *reinterpret_cast<float2*>(orow0 + 0)  = make_float2(e0[0] + bo.x, e0[1] + bo.y);
            *reinterpret_cast<float2*>(orow1 + 0)  = make_float2(e0[2] + bo.x, e0[3] + bo.y);
            bo = BO[1 * 4 + o];
            *reinterpret_cast<float2*>(orow0 + 8)  = make_float2(e1[0] + bo.x, e1[1] + bo.y);
            *reinterpret_cast<float2*>(orow1 + 8)  = make_float2(e1[2] + bo.x, e1[3] + bo.y);
            bo = BO[2 * 4 + o];
            *reinterpret_cast<float2*>(orow0 + 16) = make_float2(e2[0] + bo.x, e2[1] + bo.y);
            *reinterpret_cast<float2*>(orow1 + 16) = make_float2(e2[2] + bo.x, e2[3] + bo.y);
            bo = BO[3 * 4 + o];
            *reinterpret_cast<float2*>(orow0 + 24) = make_float2(e3[0] + bo.x, e3[1] + bo.y);
            *reinterpret_cast<float2*>(orow1 + 24) = make_float2(e3[2] + bo.x, e3[3] + bo.y);
        }
        __syncthreads();   // protect XS before next tile's staging
    }
}

// ---------------------------------------------------------------------------
extern "C" void kernel_launch(void* const* d_in, const int* in_sizes, int n_in,
                              void* d_out, int out_size) {
    const float* x     = (const float*)d_in[0];
    const float* W_ih  = (const float*)d_in[1];
    const float* W_hh  = (const float*)d_in[2];
    const float* b_ih  = (const float*)d_in[3];
    const float* b_hh  = (const float*)d_in[4];
    const float* W_out = (const float*)d_in[5];
    const float* b_out = (const float*)d_in[6];
    const float* h0    = (const float*)d_in[7];
    float* out = (float*)d_out;

    cudaFuncSetAttribute(rnn_model_kernel,
                         cudaFuncAttributeMaxDynamicSharedMemorySize, SMEM_BYTES);
    rnn_model_kernel<<<GRID, KTHREADS, SMEM_BYTES>>>(
        x, W_ih, W_hh, b_ih, b_hh, W_out, b_out, h0, out);
}

// round 4
// speedup vs baseline: 1.7072x; 1.6974x over previous
#include <cuda_runtime.h>
#include <cstdint>

// ---------------------------------------------------------------------------
// out = relu(x @ W_ih^T + (h0@W_hh^T + b_ih + b_hh)) @ W_out + b_out
// tf32 mma.sync.m16n8k8, fused two-GEMM pipeline, B-fragments amortized over
// two 16-row slabs per warp. x A-fragments loaded straight from GMEM (no smem
// staging, no syncthreads in main loop). 4 warps/CTA, 3 CTAs/SM.
// ---------------------------------------------------------------------------

static constexpr int NIN      = 64;
static constexpr int NH       = 128;
static constexpr int NOUT     = 32;
static constexpr int TILE_M   = 128;           // 4 warps x 32 rows
static constexpr int T_TOTAL  = 1048576;
static constexpr int NTILES   = T_TOTAL / TILE_M;   // 8192
static constexpr int GRID     = 456;           // 3 CTAs/SM x 152 SMs
static constexpr int KTHREADS = 128;           // 4 warps

// ---- smem byte offsets ----
static constexpr int SM_C   = 0;               // 128 f32 hidden drive
static constexpr int SM_BO  = 512;             // 32 f32 b_out
static constexpr int SM_B1  = 1024;            // W_ih B-frag pack, 32 KB
static constexpr int SM_B2  = SM_B1 + 32768;   // W_out B-frag pack, 16 KB
static constexpr int SMEM_BYTES = SM_B2 + 16384;   // 50176

__device__ __forceinline__ uint32_t f2tf(float f) {   // fp32 -> tf32 (RNA)
    uint32_t u;
    asm("cvt.rna.tf32.f32 %0, %1;" : "=r"(u) : "f"(f));
    return u;
}

__device__ __forceinline__ void mma_tf32(float& d0, float& d1, float& d2, float& d3,
                                         uint32_t a0, uint32_t a1, uint32_t a2, uint32_t a3,
                                         uint32_t b0, uint32_t b1) {
    asm volatile(
        "mma.sync.aligned.m16n8k8.row.col.f32.tf32.tf32.f32 "
        "{%0,%1,%2,%3}, {%4,%5,%6,%7}, {%8,%9}, {%0,%1,%2,%3};"
        : "+f"(d0), "+f"(d1), "+f"(d2), "+f"(d3)
        : "r"(a0), "r"(a1), "r"(a2), "r"(a3), "r"(b0), "r"(b1));
}

// ---------------------------------------------------------------------------
__global__ void __launch_bounds__(KTHREADS, 3)
rnn_model_kernel(const float* __restrict__ x,
                 const float* __restrict__ W_ih,
                 const float* __restrict__ W_hh,
                 const float* __restrict__ b_ih,
                 const float* __restrict__ b_hh,
                 const float* __restrict__ W_out,
                 const float* __restrict__ b_out,
                 const float* __restrict__ h0,
                 float* __restrict__ out)
{
    extern __shared__ char smem[];
    const int tid  = threadIdx.x;
    const int wid  = tid >> 5;
    const int lane = tid & 31;
    const int g    = lane >> 2;   // row within fragment
    const int o    = lane & 3;    // col within fragment

    uint2*  B1 = reinterpret_cast<uint2*>(smem + SM_B1);   // [8k][16n][32]
    uint2*  B2 = reinterpret_cast<uint2*>(smem + SM_B2);   // [16k][4n][32]
    float*  Cd = reinterpret_cast<float*>(smem + SM_C);
    float2* C2 = reinterpret_cast<float2*>(smem + SM_C);
    float2* BO = reinterpret_cast<float2*>(smem + SM_BO);

    // ---- one-time per-CTA fragment packs ----
    for (int e = tid; e < 8 * 16 * 32; e += KTHREADS) {
        int kj = e >> 9, nj = (e >> 5) & 15, l = e & 31;
        int row = nj * 8 + (l >> 2), col = kj * 8 + (l & 3);
        const float* p = W_ih + row * NIN + col;
        B1[e] = make_uint2(f2tf(p[0]), f2tf(p[4]));
    }
    for (int e = tid; e < 16 * 4 * 32; e += KTHREADS) {
        int kj = e >> 7, t = (e >> 5) & 3, l = e & 31;
        int row = kj * 8 + (l & 3), col = t * 8 + (l >> 2);
        const float* p = W_out + row * NOUT + col;
        B2[e] = make_uint2(f2tf(p[0]), f2tf(p[NOUT * 4]));
    }
    {   // hidden drive c = h0 @ W_hh^T + b_ih + b_hh (fp32 exact)
        float c = b_ih[tid] + b_hh[tid];
        const float4* hh = reinterpret_cast<const float4*>(W_hh + (size_t)tid * NH);
        const float4* h4 = reinterpret_cast<const float4*>(h0);
        #pragma unroll 8
        for (int q = 0; q < NH / 4; q++) {
            float4 w = hh[q], h = h4[q];
            c += w.x * h.x + w.y * h.y + w.z * h.z + w.w * h.w;
        }
        Cd[tid] = c;
    }
    if (tid < NOUT / 2) BO[tid] = make_float2(b_out[2 * tid], b_out[2 * tid + 1]);
    __syncthreads();

    const uint32_t src1 = (uint32_t)((lane & ~3) | (o >> 1));
    const uint32_t src2 = src1 + 2;
    const bool     odd  = (o & 1) != 0;

    for (int tile = blockIdx.x; tile < NTILES; tile += GRID) {
        // ---- A fragments: direct GMEM loads, two 16-row slabs ----
        // slab A rows: base+g, base+8+g; slab B rows: base+16+g, base+24+g
        const float* xr = x + ((size_t)tile * TILE_M + wid * 32 + g) * NIN + o;
        uint2 aA_lo[8], aA_hi[8], aB_lo[8], aB_hi[8];
        #pragma unroll
        for (int k = 0; k < 8; k++) {
            const float* p = xr + 8 * k;
            aA_lo[k] = make_uint2(f2tf(p[0]),            f2tf(p[4]));
            aA_hi[k] = make_uint2(f2tf(p[8 * NIN]),      f2tf(p[8 * NIN + 4]));
            aB_lo[k] = make_uint2(f2tf(p[16 * NIN]),     f2tf(p[16 * NIN + 4]));
            aB_hi[k] = make_uint2(f2tf(p[24 * NIN]),     f2tf(p[24 * NIN + 4]));
        }

        // ---- fused GEMM1 -> relu/convert -> GEMM2, B shared by both slabs ----
        float eA0[4] = {0,0,0,0}, eA1[4] = {0,0,0,0},
              eA2[4] = {0,0,0,0}, eA3[4] = {0,0,0,0};
        float eB0[4] = {0,0,0,0}, eB1[4] = {0,0,0,0},
              eB2[4] = {0,0,0,0}, eB3[4] = {0,0,0,0};

        #pragma unroll
        for (int j = 0; j < 16; j++) {
            float dA[4] = {0,0,0,0};
            float dB[4] = {0,0,0,0};
            #pragma unroll
            for (int k = 0; k < 8; k++) {
                uint2 b = B1[(k * 16 + j) * 32 + lane];
                mma_tf32(dA[0], dA[1], dA[2], dA[3],
                         aA_lo[k].x, aA_hi[k].x, aA_lo[k].y, aA_hi[k].y, b.x, b.y);
                mma_tf32(dB[0], dB[1], dB[2], dB[3],
                         aB_lo[k].x, aB_hi[k].x, aB_lo[k].y, aB_hi[k].y, b.x, b.y);
            }
            float2 cd = C2[j * 4 + o];

            uint32_t rA0 = f2tf(fmaxf(dA[0] + cd.x, 0.f));
            uint32_t rA1 = f2tf(fmaxf(dA[1] + cd.y, 0.f));
            uint32_t rA2 = f2tf(fmaxf(dA[2] + cd.x, 0.f));
            uint32_t rA3 = f2tf(fmaxf(dA[3] + cd.y, 0.f));
            uint32_t rB0 = f2tf(fmaxf(dB[0] + cd.x, 0.f));
            uint32_t rB1 = f2tf(fmaxf(dB[1] + cd.y, 0.f));
            uint32_t rB2 = f2tf(fmaxf(dB[2] + cd.x, 0.f));
            uint32_t rB3 = f2tf(fmaxf(dB[3] + cd.y, 0.f));

            // C-frag (m16n8) -> A-frag (m16k8) via shuffles, per slab
            uint32_t AA0, AA1, AA2, AA3, BB0, BB1, BB2, BB3, t0, t1;
            t0 = __shfl_sync(0xffffffffu, rA0, src1);
            t1 = __shfl_sync(0xffffffffu, rA1, src1);
            AA0 = odd ? t1 : t0;
            t0 = __shfl_sync(0xffffffffu, rA0, src2);
            t1 = __shfl_sync(0xffffffffu, rA1, src2);
            AA2 = odd ? t1 : t0;
            t0 = __shfl_sync(0xffffffffu, rA2, src1);
            t1 = __shfl_sync(0xffffffffu, rA3, src1);
            AA1 = odd ? t1 : t0;
            t0 = __shfl_sync(0xffffffffu, rA2, src2);
            t1 = __shfl_sync(0xffffffffu, rA3, src2);
            AA3 = odd ? t1 : t0;

            t0 = __shfl_sync(0xffffffffu, rB0, src1);
            t1 = __shfl_sync(0xffffffffu, rB1, src1);
            BB0 = odd ? t1 : t0;
            t0 = __shfl_sync(0xffffffffu, rB0, src2);
            t1 = __shfl_sync(0xffffffffu, rB1, src2);
            BB2 = odd ? t1 : t0;
            t0 = __shfl_sync(0xffffffffu, rB2, src1);
            t1 = __shfl_sync(0xffffffffu, rB3, src1);
            BB1 = odd ? t1 : t0;
            t0 = __shfl_sync(0xffffffffu, rB2, src2);
            t1 = __shfl_sync(0xffffffffu, rB3, src2);
            BB3 = odd ? t1 : t0;

            // GEMM2 accumulate: 4 n-tiles, B2 frag shared by both slabs
            {
                uint2 b = B2[(j * 4 + 0) * 32 + lane];
                mma_tf32(eA0[0], eA0[1], eA0[2], eA0[3], AA0, AA1, AA2, AA3, b.x, b.y);
                mma_tf32(eB0[0], eB0[1], eB0[2], eB0[3], BB0, BB1, BB2, BB3, b.x, b.y);
            }
            {
                uint2 b = B2[(j * 4 + 1) * 32 + lane];
                mma_tf32(eA1[0], eA1[1], eA1[2], eA1[3], AA0, AA1, AA2, AA3, b.x, b.y);
                mma_tf32(eB1[0], eB1[1], eB1[2], eB1[3], BB0, BB1, BB2, BB3, b.x, b.y);
            }
            {
                uint2 b = B2[(j * 4 + 2) * 32 + lane];
                mma_tf32(eA2[0], eA2[1], eA2[2], eA2[3], AA0, AA1, AA2, AA3, b.x, b.y);
                mma_tf32(eB2[0], eB2[1], eB2[2], eB2[3], BB0, BB1, BB2, BB3, b.x, b.y);
            }
            {
                uint2 b = B2[(j * 4 + 3) * 32 + lane];
                mma_tf32(eA3[0], eA3[1], eA3[2], eA3[3], AA0, AA1, AA2, AA3, b.x, b.y);
                mma_tf32(eB3[0], eB3[1], eB3[2], eB3[3], BB0, BB1, BB2, BB3, b.x, b.y);
            }
        }

        // ---- epilogue: + b_out, coalesced float2 stores, both slabs ----
        {
            const size_t rbase = (size_t)tile * TILE_M + wid * 32 + g;
            float* oA0 = out + rbase * NOUT + 2 * o;          // slab A row g
            float* oA1 = oA0 + 8 * NOUT;                       // slab A row g+8
            float* oB0 = oA0 + 16 * NOUT;                      // slab B row g+16
            float* oB1 = oA0 + 24 * NOUT;                      // slab B row g+24
            float2 bo;
            bo = BO[0 * 4 + o];
            *reinterpret_cast<float2*>(oA0 + 0)  = make_float2(eA0[0] + bo.x, eA0[1] + bo.y);
            *reinterpret_cast<float2*>(oA1 + 0)  = make_float2(eA0[2] + bo.x, eA0[3] + bo.y);
            *reinterpret_cast<float2*>(oB0 + 0)  = make_float2(eB0[0] + bo.x, eB0[1] + bo.y);
            *reinterpret_cast<float2*>(oB1 + 0)  = make_float2(eB0[2] + bo.x, eB0[3] + bo.y);
            bo = BO[1 * 4 + o];
            *reinterpret_cast<float2*>(oA0 + 8)  = make_float2(eA1[0] + bo.x, eA1[1] + bo.y);
            *reinterpret_cast<float2*>(oA1 + 8)  = make_float2(eA1[2] + bo.x, eA1[3] + bo.y);
            *reinterpret_cast<float2*>(oB0 + 8)  = make_float2(eB1[0] + bo.x, eB1[1] + bo.y);
            *reinterpret_cast<float2*>(oB1 + 8)  = make_float2(eB1[2] + bo.x, eB1[3] + bo.y);
            bo = BO[2 * 4 + o];
            *reinterpret_cast<float2*>(oA0 + 16) = make_float2(eA2[0] + bo.x, eA2[1] + bo.y);
            *reinterpret_cast<float2*>(oA1 + 16) = make_float2(eA2[2] + bo.x, eA2[3] + bo.y);
            *reinterpret_cast<float2*>(oB0 + 16) = make_float2(eB2[0] + bo.x, eB2[1] + bo.y);
            *reinterpret_cast<float2*>(oB1 + 16) = make_float2(eB2[2] + bo.x, eB2[3] + bo.y);
            bo = BO[3 * 4 + o];
            *reinterpret_cast<float2*>(oA0 + 24) = make_float2(eA3[0] + bo.x, eA3[1] + bo.y);
            *reinterpret_cast<float2*>(oA1 + 24) = make_float2(eA3[2] + bo.x, eA3[3] + bo.y);
            *reinterpret_cast<float2*>(oB0 + 24) = make_float2(eB3[0] + bo.x, eB3[1] + bo.y);
            *reinterpret_cast<float2*>(oB1 + 24) = make_float2(eB3[2] + bo.x, eB3[3] + bo.y);
        }
        // no __syncthreads: no shared state is written in the tile loop
    }
}

// ---------------------------------------------------------------------------
extern "C" void kernel_launch(void* const* d_in, const int* in_sizes, int n_in,
                              void* d_out, int out_size) {
    const float* x     = (const float*)d_in[0];
    const float* W_ih  = (const float*)d_in[1];
    const float* W_hh  = (const float*)d_in[2];
    const float* b_ih  = (const float*)d_in[3];
    const float* b_hh  = (const float*)d_in[4];
    const float* W_out = (const float*)d_in[5];
    const float* b_out = (const float*)d_in[6];
    const float* h0    = (const float*)d_in[7];
    float* out = (float*)d_out;

    cudaFuncSetAttribute(rnn_model_kernel,
                         cudaFuncAttributeMaxDynamicSharedMemorySize, SMEM_BYTES);
    rnn_model_kernel<<<GRID, KTHREADS, SMEM_BYTES>>>(
        x, W_ih, W_hh, b_ih, b_hh, W_out, b_out, h0, out);
}

// round 6
// speedup vs baseline: 1.9646x; 1.1508x over previous
#include <cuda_runtime.h>
#include <cstdint>

// ---------------------------------------------------------------------------
// out = relu(x @ W_ih^T + (h0@W_hh^T + b_ih + b_hh)) @ W_out + b_out
// tf32 mma.sync.m16n8k8, fused two-GEMM pipeline.
// Shuffle-free: GEMM1's n-axis is permuted inside the B1 pack (pi(2t)=t,
// pi(2t+1)=t+4) so its C-fragment IS GEMM2's A-fragment; GEMM1's k-axis is
// permuted (kappa(o)=2o, kappa(o+4)=2o+1) so x A-fragments are contiguous
// float2 GMEM loads. 2 slabs/warp, 4 warps/CTA, 3 CTAs/SM.
// R6 fix: CT scratch moved after B2 (was overlapping B1 -> rel_err 0.12).
// ---------------------------------------------------------------------------

static constexpr int NIN      = 64;
static constexpr int NH       = 128;
static constexpr int NOUT     = 32;
static constexpr int TILE_M   = 128;           // 4 warps x 32 rows
static constexpr int T_TOTAL  = 1048576;
static constexpr int NTILES   = T_TOTAL / TILE_M;   // 8192
static constexpr int GRID     = 456;           // 3 CTAs/SM x 152 SMs
static constexpr int KTHREADS = 128;           // 4 warps

// ---- smem byte offsets ----
static constexpr int SM_CP  = 0;               // permuted hidden drive, 64 float2
static constexpr int SM_BO  = 512;             // 32 f32 b_out
static constexpr int SM_B1  = 1024;            // W_ih B-frag pack, 32 KB
static constexpr int SM_B2  = SM_B1 + 32768;   // W_out B-frag pack, 16 KB
static constexpr int SM_CT  = SM_B2 + 16384;   // 128 f32 raw hidden drive (temp)
static constexpr int SMEM_BYTES = SM_CT + 512; // 50688

__device__ __forceinline__ uint32_t f2tf(float f) {   // fp32 -> tf32 (RNA)
    uint32_t u;
    asm("cvt.rna.tf32.f32 %0, %1;" : "=r"(u) : "f"(f));
    return u;
}

__device__ __forceinline__ void mma_tf32(float& d0, float& d1, float& d2, float& d3,
                                         uint32_t a0, uint32_t a1, uint32_t a2, uint32_t a3,
                                         uint32_t b0, uint32_t b1) {
    asm volatile(
        "mma.sync.aligned.m16n8k8.row.col.f32.tf32.tf32.f32 "
        "{%0,%1,%2,%3}, {%4,%5,%6,%7}, {%8,%9}, {%0,%1,%2,%3};"
        : "+f"(d0), "+f"(d1), "+f"(d2), "+f"(d3)
        : "r"(a0), "r"(a1), "r"(a2), "r"(a3), "r"(b0), "r"(b1));
}

// ---------------------------------------------------------------------------
__global__ void __launch_bounds__(KTHREADS, 3)
rnn_model_kernel(const float* __restrict__ x,
                 const float* __restrict__ W_ih,
                 const float* __restrict__ W_hh,
                 const float* __restrict__ b_ih,
                 const float* __restrict__ b_hh,
                 const float* __restrict__ W_out,
                 const float* __restrict__ b_out,
                 const float* __restrict__ h0,
                 float* __restrict__ out)
{
    extern __shared__ char smem[];
    const int tid  = threadIdx.x;
    const int wid  = tid >> 5;
    const int lane = tid & 31;
    const int g    = lane >> 2;   // row within fragment
    const int o    = lane & 3;    // col within fragment

    uint2*  B1 = reinterpret_cast<uint2*>(smem + SM_B1);   // [8k][16n][32]
    uint2*  B2 = reinterpret_cast<uint2*>(smem + SM_B2);   // [16k][4n][32]
    float2* CP = reinterpret_cast<float2*>(smem + SM_CP);  // permuted drive
    float*  CT = reinterpret_cast<float*>(smem + SM_CT);
    float2* BO = reinterpret_cast<float2*>(smem + SM_BO);

    // ---- one-time per-CTA fragment packs ----
    // B1: n-slot s holds logical W_ih row nj*8 + pi(s), pi(s) = (s>>1)+((s&1)<<2)
    //     k-slot o holds logical col kj*8 + 2o; k-slot o+4 -> kj*8 + 2o + 1
    for (int e = tid; e < 8 * 16 * 32; e += KTHREADS) {
        int kj = e >> 9, nj = (e >> 5) & 15, l = e & 31;
        int s   = l >> 2;
        int row = nj * 8 + ((s >> 1) + ((s & 1) << 2));
        int col = kj * 8 + 2 * (l & 3);
        const float* p = W_ih + row * NIN + col;
        B1[e] = make_uint2(f2tf(p[0]), f2tf(p[1]));
    }
    // B2: standard layout (GEMM2 A-frag is standard after the pi trick)
    for (int e = tid; e < 16 * 4 * 32; e += KTHREADS) {
        int kj = e >> 7, t = (e >> 5) & 3, l = e & 31;
        int row = kj * 8 + (l & 3), col = t * 8 + (l >> 2);
        const float* p = W_out + row * NOUT + col;
        B2[e] = make_uint2(f2tf(p[0]), f2tf(p[NOUT * 4]));
    }
    {   // hidden drive c = h0 @ W_hh^T + b_ih + b_hh (fp32 exact)
        float c = b_ih[tid] + b_hh[tid];
        const float4* hh = reinterpret_cast<const float4*>(W_hh + (size_t)tid * NH);
        const float4* h4 = reinterpret_cast<const float4*>(h0);
        #pragma unroll 8
        for (int q = 0; q < NH / 4; q++) {
            float4 w = hh[q], h = h4[q];
            c += w.x * h.x + w.y * h.y + w.z * h.z + w.w * h.w;
        }
        CT[tid] = c;
    }
    if (tid < NOUT / 2) BO[tid] = make_float2(b_out[2 * tid], b_out[2 * tid + 1]);
    __syncthreads();
    // permuted drive: CP[j*4+o] = (CT[j*8+o], CT[j*8+o+4])
    if (tid < 64) {
        int j = tid >> 2, oo = tid & 3;
        CP[tid] = make_float2(CT[j * 8 + oo], CT[j * 8 + oo + 4]);
    }
    __syncthreads();

    for (int tile = blockIdx.x; tile < NTILES; tile += GRID) {
        // ---- A fragments: contiguous float2 GMEM loads (k-permuted) ----
        // lane (g,o), k-group k: cols {8k+2o, 8k+2o+1}; rows g,g+8,g+16,g+24
        const float* xr = x + ((size_t)tile * TILE_M + wid * 32 + g) * NIN + 2 * o;
        uint2 aA_lo[8], aA_hi[8], aB_lo[8], aB_hi[8];
        #pragma unroll
        for (int k = 0; k < 8; k++) {
            const float* p = xr + 8 * k;
            float2 v0 = *reinterpret_cast<const float2*>(p);
            float2 v1 = *reinterpret_cast<const float2*>(p + 8 * NIN);
            float2 v2 = *reinterpret_cast<const float2*>(p + 16 * NIN);
            float2 v3 = *reinterpret_cast<const float2*>(p + 24 * NIN);
            aA_lo[k] = make_uint2(f2tf(v0.x), f2tf(v0.y));
            aA_hi[k] = make_uint2(f2tf(v1.x), f2tf(v1.y));
            aB_lo[k] = make_uint2(f2tf(v2.x), f2tf(v2.y));
            aB_hi[k] = make_uint2(f2tf(v3.x), f2tf(v3.y));
        }

        // ---- fused GEMM1 -> relu (in-lane) -> GEMM2 accumulate ----
        float eA0[4] = {0,0,0,0}, eA1[4] = {0,0,0,0},
              eA2[4] = {0,0,0,0}, eA3[4] = {0,0,0,0};
        float eB0[4] = {0,0,0,0}, eB1[4] = {0,0,0,0},
              eB2[4] = {0,0,0,0}, eB3[4] = {0,0,0,0};

        #pragma unroll
        for (int j = 0; j < 16; j++) {
            float dA[4] = {0,0,0,0};
            float dB[4] = {0,0,0,0};
            #pragma unroll
            for (int k = 0; k < 8; k++) {
                uint2 b = B1[(k * 16 + j) * 32 + lane];
                mma_tf32(dA[0], dA[1], dA[2], dA[3],
                         aA_lo[k].x, aA_hi[k].x, aA_lo[k].y, aA_hi[k].y, b.x, b.y);
                mma_tf32(dB[0], dB[1], dB[2], dB[3],
                         aB_lo[k].x, aB_hi[k].x, aB_lo[k].y, aB_hi[k].y, b.x, b.y);
            }
            float2 cd = CP[j * 4 + o];
            // d0 = h[g][j8+o], d1 = h[g][j8+o+4], d2 = h[g+8][j8+o], d3 = h[g+8][j8+o+4]
            uint32_t rA0 = f2tf(fmaxf(dA[0] + cd.x, 0.f));
            uint32_t rA1 = f2tf(fmaxf(dA[1] + cd.y, 0.f));
            uint32_t rA2 = f2tf(fmaxf(dA[2] + cd.x, 0.f));
            uint32_t rA3 = f2tf(fmaxf(dA[3] + cd.y, 0.f));
            uint32_t rB0 = f2tf(fmaxf(dB[0] + cd.x, 0.f));
            uint32_t rB1 = f2tf(fmaxf(dB[1] + cd.y, 0.f));
            uint32_t rB2 = f2tf(fmaxf(dB[2] + cd.x, 0.f));
            uint32_t rB3 = f2tf(fmaxf(dB[3] + cd.y, 0.f));

            // GEMM2 A-frag = (a0,a1,a2,a3) = (r0, r2, r1, r3); no data movement
            {
                uint2 b = B2[(j * 4 + 0) * 32 + lane];
                mma_tf32(eA0[0], eA0[1], eA0[2], eA0[3], rA0, rA2, rA1, rA3, b.x, b.y);
                mma_tf32(eB0[0], eB0[1], eB0[2], eB0[3], rB0, rB2, rB1, rB3, b.x, b.y);
            }
            {
                uint2 b = B2[(j * 4 + 1) * 32 + lane];
                mma_tf32(eA1[0], eA1[1], eA1[2], eA1[3], rA0, rA2, rA1, rA3, b.x, b.y);
                mma_tf32(eB1[0], eB1[1], eB1[2], eB1[3], rB0, rB2, rB1, rB3, b.x, b.y);
            }
            {
                uint2 b = B2[(j * 4 + 2) * 32 + lane];
                mma_tf32(eA2[0], eA2[1], eA2[2], eA2[3], rA0, rA2, rA1, rA3, b.x, b.y);
                mma_tf32(eB2[0], eB2[1], eB2[2], eB2[3], rB0, rB2, rB1, rB3, b.x, b.y);
            }
            {
                uint2 b = B2[(j * 4 + 3) * 32 + lane];
                mma_tf32(eA3[0], eA3[1], eA3[2], eA3[3], rA0, rA2, rA1, rA3, b.x, b.y);
                mma_tf32(eB3[0], eB3[1], eB3[2], eB3[3], rB0, rB2, rB1, rB3, b.x, b.y);
            }
        }

        // ---- epilogue: + b_out, coalesced float2 stores, both slabs ----
        {
            const size_t rbase = (size_t)tile * TILE_M + wid * 32 + g;
            float* oA0 = out + rbase * NOUT + 2 * o;          // slab A row g
            float* oA1 = oA0 + 8 * NOUT;                       // row g+8
            float* oB0 = oA0 + 16 * NOUT;                      // row g+16
            float* oB1 = oA0 + 24 * NOUT;                      // row g+24
            float2 bo;
            bo = BO[0 * 4 + o];
            *reinterpret_cast<float2*>(oA0 + 0)  = make_float2(eA0[0] + bo.x, eA0[1] + bo.y);
            *reinterpret_cast<float2*>(oA1 + 0)  = make_float2(eA0[2] + bo.x, eA0[3] + bo.y);
            *reinterpret_cast<float2*>(oB0 + 0)  = make_float2(eB0[0] + bo.x, eB0[1] + bo.y);
            *reinterpret_cast<float2*>(oB1 + 0)  = make_float2(eB0[2] + bo.x, eB0[3] + bo.y);
            bo = BO[1 * 4 + o];
            *reinterpret_cast<float2*>(oA0 + 8)  = make_float2(eA1[0] + bo.x, eA1[1] + bo.y);
            *reinterpret_cast<float2*>(oA1 + 8)  = make_float2(eA1[2] + bo.x, eA1[3] + bo.y);
            *reinterpret_cast<float2*>(oB0 + 8)  = make_float2(eB1[0] + bo.x, eB1[1] + bo.y);
            *reinterpret_cast<float2*>(oB1 + 8)  = make_float2(eB1[2] + bo.x, eB1[3] + bo.y);
            bo = BO[2 * 4 + o];
            *reinterpret_cast<float2*>(oA0 + 16) = make_float2(eA2[0] + bo.x, eA2[1] + bo.y);
            *reinterpret_cast<float2*>(oA1 + 16) = make_float2(eA2[2] + bo.x, eA2[3] + bo.y);
            *reinterpret_cast<float2*>(oB0 + 16) = make_float2(eB2[0] + bo.x, eB2[1] + bo.y);
            *reinterpret_cast<float2*>(oB1 + 16) = make_float2(eB2[2] + bo.x, eB2[3] + bo.y);
            bo = BO[3 * 4 + o];
            *reinterpret_cast<float2*>(oA0 + 24) = make_float2(eA3[0] + bo.x, eA3[1] + bo.y);
            *reinterpret_cast<float2*>(oA1 + 24) = make_float2(eA3[2] + bo.x, eA3[3] + bo.y);
            *reinterpret_cast<float2*>(oB0 + 24) = make_float2(eB3[0] + bo.x, eB3[1] + bo.y);
            *reinterpret_cast<float2*>(oB1 + 24) = make_float2(eB3[2] + bo.x, eB3[3] + bo.y);
        }
        // no __syncthreads: no shared state written in the tile loop
    }
}

// ---------------------------------------------------------------------------
extern "C" void kernel_launch(void* const* d_in, const int* in_sizes, int n_in,
                              void* d_out, int out_size) {
    const float* x     = (const float*)d_in[0];
    const float* W_ih  = (const float*)d_in[1];
    const float* W_hh  = (const float*)d_in[2];
    const float* b_ih  = (const float*)d_in[3];
    const float* b_hh  = (const float*)d_in[4];
    const float* W_out = (const float*)d_in[5];
    const float* b_out = (const float*)d_in[6];
    const float* h0    = (const float*)d_in[7];
    float* out = (float*)d_out;

    cudaFuncSetAttribute(rnn_model_kernel,
                         cudaFuncAttributeMaxDynamicSharedMemorySize, SMEM_BYTES);
    rnn_model_kernel<<<GRID, KTHREADS, SMEM_BYTES>>>(
        x, W_ih, W_hh, b_ih, b_hh, W_out, b_out, h0, out);
}

// round 7
// speedup vs baseline: 3.2698x; 1.6643x over previous
#include <cuda_runtime.h>
#include <cuda_fp16.h>
#include <cstdint>

// ---------------------------------------------------------------------------
// out = relu(x @ W_ih^T + (h0@W_hh^T + b_ih + b_hh)) @ W_out + b_out
// fp16 mma.sync.m16n8k16 (fp32 accumulate), fused two-GEMM pipeline.
// fp16 has the same 10-bit mantissa as tf32 -> same ~4e-4 rel_err, but
// 2x MACs per instruction: HMMA count and B-frag LDS traffic both halve.
// m16n8k16 layout makes GEMM1 C-frag -> GEMM2 A-frag a pure register pack
// (two adjacent n-tiles = one k16 chunk); no shuffles, no permutations.
// 2 slabs/warp, 4 warps/CTA, 3 CTAs/SM.
// ---------------------------------------------------------------------------

static constexpr int NIN      = 64;
static constexpr int NH       = 128;
static constexpr int NOUT     = 32;
static constexpr int TILE_M   = 128;           // 4 warps x 32 rows
static constexpr int T_TOTAL  = 1048576;
static constexpr int NTILES   = T_TOTAL / TILE_M;   // 8192
static constexpr int GRID     = 456;           // 3 CTAs/SM x 152 SMs
static constexpr int KTHREADS = 128;           // 4 warps

// ---- smem byte offsets ----
static constexpr int SM_CP  = 0;               // hidden drive pairs, 64 float2
static constexpr int SM_BO  = 512;             // 32 f32 b_out
static constexpr int SM_B1  = 1024;            // W_ih fp16 B-frag pack, 16 KB
static constexpr int SM_B2  = SM_B1 + 16384;   // W_out fp16 B-frag pack, 8 KB
static constexpr int SM_CT  = SM_B2 + 8192;    // 128 f32 raw hidden drive (temp)
static constexpr int SMEM_BYTES = SM_CT + 512; // 26112

__device__ __forceinline__ uint32_t packh2(float lo, float hi) {
    uint32_t r;
    asm("cvt.rn.f16x2.f32 %0, %1, %2;" : "=r"(r) : "f"(hi), "f"(lo));
    return r;
}

__device__ __forceinline__ void mma_fp16(float& d0, float& d1, float& d2, float& d3,
                                         uint32_t a0, uint32_t a1, uint32_t a2, uint32_t a3,
                                         uint32_t b0, uint32_t b1) {
    asm volatile(
        "mma.sync.aligned.m16n8k16.row.col.f32.f16.f16.f32 "
        "{%0,%1,%2,%3}, {%4,%5,%6,%7}, {%8,%9}, {%0,%1,%2,%3};"
        : "+f"(d0), "+f"(d1), "+f"(d2), "+f"(d3)
        : "r"(a0), "r"(a1), "r"(a2), "r"(a3), "r"(b0), "r"(b1));
}

// ---------------------------------------------------------------------------
__global__ void __launch_bounds__(KTHREADS, 3)
rnn_model_kernel(const float* __restrict__ x,
                 const float* __restrict__ W_ih,
                 const float* __restrict__ W_hh,
                 const float* __restrict__ b_ih,
                 const float* __restrict__ b_hh,
                 const float* __restrict__ W_out,
                 const float* __restrict__ b_out,
                 const float* __restrict__ h0,
                 float* __restrict__ out)
{
    extern __shared__ char smem[];
    const int tid  = threadIdx.x;
    const int wid  = tid >> 5;
    const int lane = tid & 31;
    const int g    = lane >> 2;   // row within fragment
    const int o    = lane & 3;    // col pair within fragment

    uint2*  B1 = reinterpret_cast<uint2*>(smem + SM_B1);   // [4c][16j][32]
    uint2*  B2 = reinterpret_cast<uint2*>(smem + SM_B2);   // [8q][4t][32]
    float2* CP = reinterpret_cast<float2*>(smem + SM_CP);
    float*  CT = reinterpret_cast<float*>(smem + SM_CT);
    float2* BO = reinterpret_cast<float2*>(smem + SM_BO);

    // ---- one-time per-CTA fragment packs (fp16) ----
    // B1 (GEMM1, B = W_ih^T, k16 x n8 col-major frag):
    //   reg0 = { W_ih[8j+g][16c+2o],   W_ih[8j+g][16c+2o+1] }
    //   reg1 = { W_ih[8j+g][16c+2o+8], W_ih[8j+g][16c+2o+9] }
    for (int e = tid; e < 4 * 16 * 32; e += KTHREADS) {
        int c = e >> 9, j = (e >> 5) & 15, l = e & 31;
        int row = 8 * j + (l >> 2);
        int col = 16 * c + 2 * (l & 3);
        const float* p = W_ih + row * NIN + col;
        B1[e] = make_uint2(packh2(p[0], p[1]), packh2(p[8], p[9]));
    }
    // B2 (GEMM2, B = W_out [k=128][n=32]):
    //   reg0 = { W_out[16q+2o][8t+g],   W_out[16q+2o+1][8t+g] }
    //   reg1 = { W_out[16q+2o+8][8t+g], W_out[16q+2o+9][8t+g] }
    for (int e = tid; e < 8 * 4 * 32; e += KTHREADS) {
        int q = e >> 7, t = (e >> 5) & 3, l = e & 31;
        int row = 16 * q + 2 * (l & 3);
        int col = 8 * t + (l >> 2);
        const float* p = W_out + row * NOUT + col;
        B2[e] = make_uint2(packh2(p[0],        p[NOUT]),
                           packh2(p[8 * NOUT], p[9 * NOUT]));
    }
    {   // hidden drive c = h0 @ W_hh^T + b_ih + b_hh (fp32 exact)
        float c = b_ih[tid] + b_hh[tid];
        const float4* hh = reinterpret_cast<const float4*>(W_hh + (size_t)tid * NH);
        const float4* h4 = reinterpret_cast<const float4*>(h0);
        #pragma unroll 8
        for (int q = 0; q < NH / 4; q++) {
            float4 w = hh[q], h = h4[q];
            c += w.x * h.x + w.y * h.y + w.z * h.z + w.w * h.w;
        }
        CT[tid] = c;
    }
    if (tid < NOUT / 2) BO[tid] = make_float2(b_out[2 * tid], b_out[2 * tid + 1]);
    __syncthreads();
    // drive pairs: CP[j*4+o] = (CT[8j+2o], CT[8j+2o+1])  (natural order)
    if (tid < 64) {
        int j = tid >> 2, oo = tid & 3;
        CP[tid] = make_float2(CT[8 * j + 2 * oo], CT[8 * j + 2 * oo + 1]);
    }
    __syncthreads();

    for (int tile = blockIdx.x; tile < NTILES; tile += GRID) {
        // ---- A fragments (x, fp16): contiguous float2 loads, 4 k16-chunks ----
        // lane (g,o), chunk c: cols {16c+2o,+1} and {16c+2o+8,+9};
        // slab A rows g, g+8; slab B rows g+16, g+24.
        const float* xr = x + ((size_t)tile * TILE_M + wid * 32 + g) * NIN + 2 * o;
        uint32_t aA[4][4], aB[4][4];
        #pragma unroll
        for (int c = 0; c < 4; c++) {
            const float* p = xr + 16 * c;
            float2 v;
            v = *reinterpret_cast<const float2*>(p);                aA[c][0] = packh2(v.x, v.y);
            v = *reinterpret_cast<const float2*>(p + 8 * NIN);      aA[c][1] = packh2(v.x, v.y);
            v = *reinterpret_cast<const float2*>(p + 8);            aA[c][2] = packh2(v.x, v.y);
            v = *reinterpret_cast<const float2*>(p + 8 * NIN + 8);  aA[c][3] = packh2(v.x, v.y);
            v = *reinterpret_cast<const float2*>(p + 16 * NIN);     aB[c][0] = packh2(v.x, v.y);
            v = *reinterpret_cast<const float2*>(p + 24 * NIN);     aB[c][1] = packh2(v.x, v.y);
            v = *reinterpret_cast<const float2*>(p + 16 * NIN + 8); aB[c][2] = packh2(v.x, v.y);
            v = *reinterpret_cast<const float2*>(p + 24 * NIN + 8); aB[c][3] = packh2(v.x, v.y);
        }

        // ---- fused GEMM1 -> relu/pack -> GEMM2 ----
        float eA0[4] = {0,0,0,0}, eA1[4] = {0,0,0,0},
              eA2[4] = {0,0,0,0}, eA3[4] = {0,0,0,0};
        float eB0[4] = {0,0,0,0}, eB1[4] = {0,0,0,0},
              eB2[4] = {0,0,0,0}, eB3[4] = {0,0,0,0};

        #pragma unroll
        for (int q = 0; q < 8; q++) {          // k16-chunk of GEMM2 = j-pair
            uint32_t hA[4], hB[4];             // GEMM2 A-frags, both slabs
            #pragma unroll
            for (int jj = 0; jj < 2; jj++) {
                const int j = 2 * q + jj;
                float dA[4] = {0,0,0,0};
                float dB[4] = {0,0,0,0};
                #pragma unroll
                for (int c = 0; c < 4; c++) {
                    uint2 b = B1[(c * 16 + j) * 32 + lane];
                    mma_fp16(dA[0], dA[1], dA[2], dA[3],
                             aA[c][0], aA[c][1], aA[c][2], aA[c][3], b.x, b.y);
                    mma_fp16(dB[0], dB[1], dB[2], dB[3],
                             aB[c][0], aB[c][1], aB[c][2], aB[c][3], b.x, b.y);
                }
                float2 cd = CP[j * 4 + o];
                // c0,c1 = row g cols 8j+2o,+1; c2,c3 = row g+8
                hA[jj * 2 + 0] = packh2(fmaxf(dA[0] + cd.x, 0.f),
                                        fmaxf(dA[1] + cd.y, 0.f));
                hA[jj * 2 + 1] = packh2(fmaxf(dA[2] + cd.x, 0.f),
                                        fmaxf(dA[3] + cd.y, 0.f));
                hB[jj * 2 + 0] = packh2(fmaxf(dB[0] + cd.x, 0.f),
                                        fmaxf(dB[1] + cd.y, 0.f));
                hB[jj * 2 + 1] = packh2(fmaxf(dB[2] + cd.x, 0.f),
                                        fmaxf(dB[3] + cd.y, 0.f));
            }
            // GEMM2 chunk q: A-frag = {h[0], h[1], h[2], h[3]}
            {
                uint2 b = B2[(q * 4 + 0) * 32 + lane];
                mma_fp16(eA0[0], eA0[1], eA0[2], eA0[3], hA[0], hA[1], hA[2], hA[3], b.x, b.y);
                mma_fp16(eB0[0], eB0[1], eB0[2], eB0[3], hB[0], hB[1], hB[2], hB[3], b.x, b.y);
            }
            {
                uint2 b = B2[(q * 4 + 1) * 32 + lane];
                mma_fp16(eA1[0], eA1[1], eA1[2], eA1[3], hA[0], hA[1], hA[2], hA[3], b.x, b.y);
                mma_fp16(eB1[0], eB1[1], eB1[2], eB1[3], hB[0], hB[1], hB[2], hB[3], b.x, b.y);
            }
            {
                uint2 b = B2[(q * 4 + 2) * 32 + lane];
                mma_fp16(eA2[0], eA2[1], eA2[2], eA2[3], hA[0], hA[1], hA[2], hA[3], b.x, b.y);
                mma_fp16(eB2[0], eB2[1], eB2[2], eB2[3], hB[0], hB[1], hB[2], hB[3], b.x, b.y);
            }
            {
                uint2 b = B2[(q * 4 + 3) * 32 + lane];
                mma_fp16(eA3[0], eA3[1], eA3[2], eA3[3], hA[0], hA[1], hA[2], hA[3], b.x, b.y);
                mma_fp16(eB3[0], eB3[1], eB3[2], eB3[3], hB[0], hB[1], hB[2], hB[3], b.x, b.y);
            }
        }

        // ---- epilogue: + b_out, coalesced float2 stores, both slabs ----
        {
            const size_t rbase = (size_t)tile * TILE_M + wid * 32 + g;
            float* oA0 = out + rbase * NOUT + 2 * o;          // slab A row g
            float* oA1 = oA0 + 8 * NOUT;                       // row g+8
            float* oB0 = oA0 + 16 * NOUT;                      // row g+16
            float* oB1 = oA0 + 24 * NOUT;                      // row g+24
            float2 bo;
            bo = BO[0 * 4 + o];
            *reinterpret_cast<float2*>(oA0 + 0)  = make_float2(eA0[0] + bo.x, eA0[1] + bo.y);
            *reinterpret_cast<float2*>(oA1 + 0)  = make_float2(eA0[2] + bo.x, eA0[3] + bo.y);
            *reinterpret_cast<float2*>(oB0 + 0)  = make_float2(eB0[0] + bo.x, eB0[1] + bo.y);
            *reinterpret_cast<float2*>(oB1 + 0)  = make_float2(eB0[2] + bo.x, eB0[3] + bo.y);
            bo = BO[1 * 4 + o];
            *reinterpret_cast<float2*>(oA0 + 8)  = make_float2(eA1[0] + bo.x, eA1[1] + bo.y);
            *reinterpret_cast<float2*>(oA1 + 8)  = make_float2(eA1[2] + bo.x, eA1[3] + bo.y);
            *reinterpret_cast<float2*>(oB0 + 8)  = make_float2(eB1[0] + bo.x, eB1[1] + bo.y);
            *reinterpret_cast<float2*>(oB1 + 8)  = make_float2(eB1[2] + bo.x, eB1[3] + bo.y);
            bo = BO[2 * 4 + o];
            *reinterpret_cast<float2*>(oA0 + 16) = make_float2(eA2[0] + bo.x, eA2[1] + bo.y);
            *reinterpret_cast<float2*>(oA1 + 16) = make_float2(eA2[2] + bo.x, eA2[3] + bo.y);
            *reinterpret_cast<float2*>(oB0 + 16) = make_float2(eB2[0] + bo.x, eB2[1] + bo.y);
            *reinterpret_cast<float2*>(oB1 + 16) = make_float2(eB2[2] + bo.x, eB2[3] + bo.y);
            bo = BO[3 * 4 + o];
            *reinterpret_cast<float2*>(oA0 + 24) = make_float2(eA3[0] + bo.x, eA3[1] + bo.y);
            *reinterpret_cast<float2*>(oA1 + 24) = make_float2(eA3[2] + bo.x, eA3[3] + bo.y);
            *reinterpret_cast<float2*>(oB0 + 24) = make_float2(eB3[0] + bo.x, eB3[1] + bo.y);
            *reinterpret_cast<float2*>(oB1 + 24) = make_float2(eB3[2] + bo.x, eB3[3] + bo.y);
        }
        // no __syncthreads: no shared state written in the tile loop
    }
}

// ---------------------------------------------------------------------------
extern "C" void kernel_launch(void* const* d_in, const int* in_sizes, int n_in,
                              void* d_out, int out_size) {
    const float* x     = (const float*)d_in[0];
    const float* W_ih  = (const float*)d_in[1];
    const float* W_hh  = (const float*)d_in[2];
    const float* b_ih  = (const float*)d_in[3];
    const float* b_hh  = (const float*)d_in[4];
    const float* W_out = (const float*)d_in[5];
    const float* b_out = (const float*)d_in[6];
    const float* h0    = (const float*)d_in[7];
    float* out = (float*)d_out;

    cudaFuncSetAttribute(rnn_model_kernel,
                         cudaFuncAttributeMaxDynamicSharedMemorySize, SMEM_BYTES);
    rnn_model_kernel<<<GRID, KTHREADS, SMEM_BYTES>>>(
        x, W_ih, W_hh, b_ih, b_hh, W_out, b_out, h0, out);
}

// round 8
// speedup vs baseline: 3.3785x; 1.0332x over previous
#include <cuda_runtime.h>
#include <cuda_fp16.h>
#include <cstdint>

// ---------------------------------------------------------------------------
// out = relu(x @ W_ih^T + (h0@W_hh^T + b_ih + b_hh)) @ W_out + b_out
// fp16 mma.sync.m16n8k16 (fp32 accumulate), fused two-GEMM pipeline.
// R8: x staged per-warp through smem: coalesced LDG.128 -> fp16 STS.64 ->
// conflict-free LDS.32 fragment reads (pitch 36 words => bank = 4g+o).
// Replaces sector-fragmented direct LDG.64 A-loads (8 wf each -> L1 bound).
// Per-warp buffers: only __syncwarp needed. 4 warps/CTA, 4 CTAs/SM.
// ---------------------------------------------------------------------------

static constexpr int NIN      = 64;
static constexpr int NH       = 128;
static constexpr int NOUT     = 32;
static constexpr int TILE_M   = 128;           // 4 warps x 32 rows
static constexpr int T_TOTAL  = 1048576;
static constexpr int NTILES   = T_TOTAL / TILE_M;   // 8192
static constexpr int GRID     = 608;           // 4 CTAs/SM x 152 SMs
static constexpr int KTHREADS = 128;           // 4 warps

// x staging: per-warp fp16 buffer, 32 rows x 36 words (uint32=fp16x2), 4608 B
static constexpr int XPITCH_W = 36;            // words per row (== 4 mod 32)
static constexpr int XBUF_B   = 32 * XPITCH_W * 4;   // 4608

// ---- smem byte offsets ----
static constexpr int SM_CP  = 0;               // hidden drive pairs, 64 float2
static constexpr int SM_BO  = 512;             // 32 f32 b_out
static constexpr int SM_B1  = 1024;            // W_ih fp16 B-frag pack, 16 KB
static constexpr int SM_B2  = SM_B1 + 16384;   // W_out fp16 B-frag pack, 8 KB
static constexpr int SM_CT  = SM_B2 + 8192;    // 128 f32 raw hidden drive (temp)
static constexpr int SM_X   = SM_CT + 512;     // 4 x 4608 per-warp x buffers
static constexpr int SMEM_BYTES = SM_X + 4 * XBUF_B;   // 44544

__device__ __forceinline__ uint32_t packh2(float lo, float hi) {
    uint32_t r;
    asm("cvt.rn.f16x2.f32 %0, %1, %2;" : "=r"(r) : "f"(hi), "f"(lo));
    return r;
}

__device__ __forceinline__ void mma_fp16(float& d0, float& d1, float& d2, float& d3,
                                         uint32_t a0, uint32_t a1, uint32_t a2, uint32_t a3,
                                         uint32_t b0, uint32_t b1) {
    asm volatile(
        "mma.sync.aligned.m16n8k16.row.col.f32.f16.f16.f32 "
        "{%0,%1,%2,%3}, {%4,%5,%6,%7}, {%8,%9}, {%0,%1,%2,%3};"
        : "+f"(d0), "+f"(d1), "+f"(d2), "+f"(d3)
        : "r"(a0), "r"(a1), "r"(a2), "r"(a3), "r"(b0), "r"(b1));
}

// ---------------------------------------------------------------------------
__global__ void __launch_bounds__(KTHREADS, 4)
rnn_model_kernel(const float* __restrict__ x,
                 const float* __restrict__ W_ih,
                 const float* __restrict__ W_hh,
                 const float* __restrict__ b_ih,
                 const float* __restrict__ b_hh,
                 const float* __restrict__ W_out,
                 const float* __restrict__ b_out,
                 const float* __restrict__ h0,
                 float* __restrict__ out)
{
    extern __shared__ char smem[];
    const int tid  = threadIdx.x;
    const int wid  = tid >> 5;
    const int lane = tid & 31;
    const int g    = lane >> 2;   // row within fragment
    const int o    = lane & 3;    // col pair within fragment

    uint2*  B1 = reinterpret_cast<uint2*>(smem + SM_B1);   // [4c][16j][32]
    uint2*  B2 = reinterpret_cast<uint2*>(smem + SM_B2);   // [8q][4t][32]
    float2* CP = reinterpret_cast<float2*>(smem + SM_CP);
    float*  CT = reinterpret_cast<float*>(smem + SM_CT);
    float2* BO = reinterpret_cast<float2*>(smem + SM_BO);
    uint32_t* XW = reinterpret_cast<uint32_t*>(smem + SM_X + wid * XBUF_B);

    // ---- one-time per-CTA fragment packs (fp16) ----
    // B1 (GEMM1, B = W_ih^T, k16 x n8 col-major frag):
    //   reg0 = { W_ih[8j+g][16c+2o],   W_ih[8j+g][16c+2o+1] }
    //   reg1 = { W_ih[8j+g][16c+2o+8], W_ih[8j+g][16c+2o+9] }
    for (int e = tid; e < 4 * 16 * 32; e += KTHREADS) {
        int c = e >> 9, j = (e >> 5) & 15, l = e & 31;
        int row = 8 * j + (l >> 2);
        int col = 16 * c + 2 * (l & 3);
        const float* p = W_ih + row * NIN + col;
        B1[e] = make_uint2(packh2(p[0], p[1]), packh2(p[8], p[9]));
    }
    // B2 (GEMM2, B = W_out [k=128][n=32]):
    //   reg0 = { W_out[16q+2o][8t+g],   W_out[16q+2o+1][8t+g] }
    //   reg1 = { W_out[16q+2o+8][8t+g], W_out[16q+2o+9][8t+g] }
    for (int e = tid; e < 8 * 4 * 32; e += KTHREADS) {
        int q = e >> 7, t = (e >> 5) & 3, l = e & 31;
        int row = 16 * q + 2 * (l & 3);
        int col = 8 * t + (l >> 2);
        const float* p = W_out + row * NOUT + col;
        B2[e] = make_uint2(packh2(p[0],        p[NOUT]),
                           packh2(p[8 * NOUT], p[9 * NOUT]));
    }
    {   // hidden drive c = h0 @ W_hh^T + b_ih + b_hh (fp32 exact)
        float c = b_ih[tid] + b_hh[tid];
        const float4* hh = reinterpret_cast<const float4*>(W_hh + (size_t)tid * NH);
        const float4* h4 = reinterpret_cast<const float4*>(h0);
        #pragma unroll 8
        for (int q = 0; q < NH / 4; q++) {
            float4 w = hh[q], h = h4[q];
            c += w.x * h.x + w.y * h.y + w.z * h.z + w.w * h.w;
        }
        CT[tid] = c;
    }
    if (tid < NOUT / 2) BO[tid] = make_float2(b_out[2 * tid], b_out[2 * tid + 1]);
    __syncthreads();
    // drive pairs: CP[j*4+o] = (CT[8j+2o], CT[8j+2o+1])
    if (tid < 64) {
        int j = tid >> 2, oo = tid & 3;
        CP[tid] = make_float2(CT[8 * j + 2 * oo], CT[8 * j + 2 * oo + 1]);
    }
    __syncthreads();

    for (int tile = blockIdx.x; tile < NTILES; tile += GRID) {
        // ---- stage this warp's 32 x-rows: coalesced LDG.128 -> fp16 smem ----
        const float4* xt = reinterpret_cast<const float4*>(
            x + ((size_t)tile * TILE_M + wid * 32) * NIN);
        #pragma unroll
        for (int i = 0; i < 16; i++) {
            int f = i * 32 + lane;            // float4 index, 0..511
            float4 v = xt[f];
            int row = f >> 4;                 // 16 float4 per row
            int w   = (f & 15) * 2;           // word (fp16x2) index, even
            *reinterpret_cast<uint2*>(XW + row * XPITCH_W + w) =
                make_uint2(packh2(v.x, v.y), packh2(v.z, v.w));
        }
        __syncwarp();

        // ---- A fragments from smem: conflict-free LDS.32 (bank = 4g+o) ----
        // chunk c: word 8c+o = cols {16c+2o,+1}; word 8c+o+4 = cols {+8,+9}
        uint32_t aA[4][4], aB[4][4];
        {
            const uint32_t* r0 = XW + g * XPITCH_W + o;          // row g
            const uint32_t* r1 = r0 + 8 * XPITCH_W;              // row g+8
            const uint32_t* r2 = r0 + 16 * XPITCH_W;             // row g+16
            const uint32_t* r3 = r0 + 24 * XPITCH_W;             // row g+24
            #pragma unroll
            for (int c = 0; c < 4; c++) {
                aA[c][0] = r0[8 * c];
                aA[c][1] = r1[8 * c];
                aA[c][2] = r0[8 * c + 4];
                aA[c][3] = r1[8 * c + 4];
                aB[c][0] = r2[8 * c];
                aB[c][1] = r3[8 * c];
                aB[c][2] = r2[8 * c + 4];
                aB[c][3] = r3[8 * c + 4];
            }
        }
        __syncwarp();

        // ---- fused GEMM1 -> relu/pack -> GEMM2 ----
        float eA0[4] = {0,0,0,0}, eA1[4] = {0,0,0,0},
              eA2[4] = {0,0,0,0}, eA3[4] = {0,0,0,0};
        float eB0[4] = {0,0,0,0}, eB1[4] = {0,0,0,0},
              eB2[4] = {0,0,0,0}, eB3[4] = {0,0,0,0};

        #pragma unroll
        for (int q = 0; q < 8; q++) {          // k16-chunk of GEMM2 = j-pair
            uint32_t hA[4], hB[4];             // GEMM2 A-frags, both slabs
            #pragma unroll
            for (int jj = 0; jj < 2; jj++) {
                const int j = 2 * q + jj;
                float dA[4] = {0,0,0,0};
                float dB[4] = {0,0,0,0};
                #pragma unroll
                for (int c = 0; c < 4; c++) {
                    uint2 b = B1[(c * 16 + j) * 32 + lane];
                    mma_fp16(dA[0], dA[1], dA[2], dA[3],
                             aA[c][0], aA[c][1], aA[c][2], aA[c][3], b.x, b.y);
                    mma_fp16(dB[0], dB[1], dB[2], dB[3],
                             aB[c][0], aB[c][1], aB[c][2], aB[c][3], b.x, b.y);
                }
                float2 cd = CP[j * 4 + o];
                hA[jj * 2 + 0] = packh2(fmaxf(dA[0] + cd.x, 0.f),
                                        fmaxf(dA[1] + cd.y, 0.f));
                hA[jj * 2 + 1] = packh2(fmaxf(dA[2] + cd.x, 0.f),
                                        fmaxf(dA[3] + cd.y, 0.f));
                hB[jj * 2 + 0] = packh2(fmaxf(dB[0] + cd.x, 0.f),
                                        fmaxf(dB[1] + cd.y, 0.f));
                hB[jj * 2 + 1] = packh2(fmaxf(dB[2] + cd.x, 0.f),
                                        fmaxf(dB[3] + cd.y, 0.f));
            }
            // GEMM2 chunk q
            {
                uint2 b = B2[(q * 4 + 0) * 32 + lane];
                mma_fp16(eA0[0], eA0[1], eA0[2], eA0[3], hA[0], hA[1], hA[2], hA[3], b.x, b.y);
                mma_fp16(eB0[0], eB0[1], eB0[2], eB0[3], hB[0], hB[1], hB[2], hB[3], b.x, b.y);
            }
            {
                uint2 b = B2[(q * 4 + 1) * 32 + lane];
                mma_fp16(eA1[0], eA1[1], eA1[2], eA1[3], hA[0], hA[1], hA[2], hA[3], b.x, b.y);
                mma_fp16(eB1[0], eB1[1], eB1[2], eB1[3], hB[0], hB[1], hB[2], hB[3], b.x, b.y);
            }
            {
                uint2 b = B2[(q * 4 + 2) * 32 + lane];
                mma_fp16(eA2[0], eA2[1], eA2[2], eA2[3], hA[0], hA[1], hA[2], hA[3], b.x, b.y);
                mma_fp16(eB2[0], eB2[1], eB2[2], eB2[3], hB[0], hB[1], hB[2], hB[3], b.x, b.y);
            }
            {
                uint2 b = B2[(q * 4 + 3) * 32 + lane];
                mma_fp16(eA3[0], eA3[1], eA3[2], eA3[3], hA[0], hA[1], hA[2], hA[3], b.x, b.y);
                mma_fp16(eB3[0], eB3[1], eB3[2], eB3[3], hB[0], hB[1], hB[2], hB[3], b.x, b.y);
            }
        }

        // ---- epilogue: + b_out, coalesced float2 stores, both slabs ----
        {
            const size_t rbase = (size_t)tile * TILE_M + wid * 32 + g;
            float* oA0 = out + rbase * NOUT + 2 * o;          // slab A row g
            float* oA1 = oA0 + 8 * NOUT;                       // row g+8
            float* oB0 = oA0 + 16 * NOUT;                      // row g+16
            float* oB1 = oA0 + 24 * NOUT;                      // row g+24
            float2 bo;
            bo = BO[0 * 4 + o];
            *reinterpret_cast<float2*>(oA0 + 0)  = make_float2(eA0[0] + bo.x, eA0[1] + bo.y);
            *reinterpret_cast<float2*>(oA1 + 0)  = make_float2(eA0[2] + bo.x, eA0[3] + bo.y);
            *reinterpret_cast<float2*>(oB0 + 0)  = make_float2(eB0[0] + bo.x, eB0[1] + bo.y);
            *reinterpret_cast<float2*>(oB1 + 0)  = make_float2(eB0[2] + bo.x, eB0[3] + bo.y);
            bo = BO[1 * 4 + o];
            *reinterpret_cast<float2*>(oA0 + 8)  = make_float2(eA1[0] + bo.x, eA1[1] + bo.y);
            *reinterpret_cast<float2*>(oA1 + 8)  = make_float2(eA1[2] + bo.x, eA1[3] + bo.y);
            *reinterpret_cast<float2*>(oB0 + 8)  = make_float2(eB1[0] + bo.x, eB1[1] + bo.y);
            *reinterpret_cast<float2*>(oB1 + 8)  = make_float2(eB1[2] + bo.x, eB1[3] + bo.y);
            bo = BO[2 * 4 + o];
            *reinterpret_cast<float2*>(oA0 + 16) = make_float2(eA2[0] + bo.x, eA2[1] + bo.y);
            *reinterpret_cast<float2*>(oA1 + 16) = make_float2(eA2[2] + bo.x, eA2[3] + bo.y);
            *reinterpret_cast<float2*>(oB0 + 16) = make_float2(eB2[0] + bo.x, eB2[1] + bo.y);
            *reinterpret_cast<float2*>(oB1 + 16) = make_float2(eB2[2] + bo.x, eB2[3] + bo.y);
            bo = BO[3 * 4 + o];
            *reinterpret_cast<float2*>(oA0 + 24) = make_float2(eA3[0] + bo.x, eA3[1] + bo.y);
            *reinterpret_cast<float2*>(oA1 + 24) = make_float2(eA3[2] + bo.x, eA3[3] + bo.y);
            *reinterpret_cast<float2*>(oB0 + 24) = make_float2(eB3[0] + bo.x, eB3[1] + bo.y);
            *reinterpret_cast<float2*>(oB1 + 24) = make_float2(eB3[2] + bo.x, eB3[3] + bo.y);
        }
        // per-warp x buffer: next iteration's writes are ordered by __syncwarp
        __syncwarp();
    }
}

// ---------------------------------------------------------------------------
extern "C" void kernel_launch(void* const* d_in, const int* in_sizes, int n_in,
                              void* d_out, int out_size) {
    const float* x     = (const float*)d_in[0];
    const float* W_ih  = (const float*)d_in[1];
    const float* W_hh  = (const float*)d_in[2];
    const float* b_ih  = (const float*)d_in[3];
    const float* b_hh  = (const float*)d_in[4];
    const float* W_out = (const float*)d_in[5];
    const float* b_out = (const float*)d_in[6];
    const float* h0    = (const float*)d_in[7];
    float* out = (float*)d_out;

    cudaFuncSetAttribute(rnn_model_kernel,
                         cudaFuncAttributeMaxDynamicSharedMemorySize, SMEM_BYTES);
    rnn_model_kernel<<<GRID, KTHREADS, SMEM_BYTES>>>(
        x, W_ih, W_hh, b_ih, b_hh, W_out, b_out, h0, out);
}